// round 14
// baseline (speedup 1.0000x reference)
#include <cuda_runtime.h>
#include <math.h>
#include <cstdint>

#define NN    50000
#define EE    800000
#define DIN   256
#define DOUTC 256
#define ZMIX  0.8f
#define EPSGN 1e-5f

// ---------------- scratch (static device globals; no allocation) ----------------
__device__ float g_ew[EE];
__device__ float g_deg[NN];
__device__ float g_dinv[NN];
__device__ int   g_cnt[NN];
__device__ int   g_offs[NN + 1];
__device__ int   g_cursor[NN];
__device__ int   g_ccol[EE];
__device__ float g_cw[EE];
__device__ float g_xm[NN * DOUTC];
__device__ float g_agg[NN * DOUTC];
__device__ float g_colsum[DOUTC];
__device__ float g_colsq[DOUTC];
__device__ float g_ns[DOUTC];
__device__ float g_nt[DOUTC];
__device__ int   g_bsum[64];
__device__ int   g_boff[64];

// weights: [n][K], RNA-rounded tf32, each 16-k group permuted so word (c*4+q)
// holds W[k_local=c+4q][n] => one LDS.128 per B fragment pair on compute side,
// and a straight contiguous copy on the staging side (cp.async-able).
__device__ float g_Wt0T[256 * 256];
__device__ float g_Wt1T[256 * 256];
__device__ float g_Wc0T[256 * 512];
__device__ float g_Wc1T[256 * 512];

__device__ __forceinline__ float to_tf32(float x) {
    float r;
    asm("cvt.rna.tf32.f32 %0, %1;" : "=f"(r) : "f"(x));
    return r;
}
__device__ __forceinline__ uint32_t fbits(float x) { return __float_as_uint(x); }
__device__ __forceinline__ uint32_t smem_u32(const void* p) {
    uint32_t a;
    asm("{ .reg .u64 t; cvta.to.shared.u64 t, %1; cvt.u32.u64 %0, t; }" : "=r"(a) : "l"(p));
    return a;
}

#define CP_ASYNC16(dst_u32, src_ptr) \
    asm volatile("cp.async.cg.shared.global [%0], [%1], 16;" :: "r"(dst_u32), "l"(src_ptr))
#define CP_COMMIT() asm volatile("cp.async.commit_group;" ::: "memory")
#define CP_WAIT0()  asm volatile("cp.async.wait_group 0;" ::: "memory")

#define MMA_TF32(C, A, B0, B1) \
    asm volatile("mma.sync.aligned.m16n8k8.row.col.f32.tf32.tf32.f32 " \
        "{%0,%1,%2,%3}, {%4,%5,%6,%7}, {%8,%9}, {%0,%1,%2,%3};" \
        : "+f"((C)[0]), "+f"((C)[1]), "+f"((C)[2]), "+f"((C)[3]) \
        : "r"((A)[0]), "r"((A)[1]), "r"((A)[2]), "r"((A)[3]), "r"(B0), "r"(B1))

__device__ __forceinline__ int decode_idx(unsigned int w) {
    int v = (w >= 0x3F000000u) ? (int)__uint_as_float(w) : (int)w;
    v = v < 0 ? 0 : (v >= NN ? NN - 1 : v);
    return v;
}

// ---------------- init ----------------
__global__ void init_kernel() {
    int i = blockIdx.x * blockDim.x + threadIdx.x;
    int stride = gridDim.x * blockDim.x;
    for (int j = i; j < NN; j += stride) { g_deg[j] = 0.f; g_cnt[j] = 0; }
    for (int j = i; j < DOUTC; j += stride) { g_colsum[j] = 0.f; g_colsq[j] = 0.f; }
}

// ---------------- weight prep: [K,N] -> [n][K] permuted-16-group, RNA tf32 ----------------
__global__ __launch_bounds__(256) void prep_weights_kernel(const float* __restrict__ W, int K, int sel) {
    float* dst = (sel == 0) ? g_Wt0T : (sel == 1) ? g_Wt1T : (sel == 2) ? g_Wc0T : g_Wc1T;
    int idx = blockIdx.x * 256 + threadIdx.x;   // over K*64 float4s
    if (idx >= K * 64) return;
    int k = idx >> 6;
    int n4 = idx & 63;
    float4 v = ((const float4*)W)[idx];         // W[k][4*n4 .. 4*n4+3]
    int kl = k & 15;
    int off = (k >> 4) * 16 + (kl & 3) * 4 + (kl >> 2);
    float vv[4] = {v.x, v.y, v.z, v.w};
    #pragma unroll
    for (int j = 0; j < 4; j++)
        dst[(size_t)(n4 * 4 + j) * K + off] = to_tf32(vv[j]);
}

// ---------------- edge MLP ----------------
__global__ __launch_bounds__(256) void edge_mlp_kernel(
    const float* __restrict__ ea, const unsigned int* __restrict__ ei, int estride,
    const float* __restrict__ Wm1, const float* __restrict__ bm1,
    const float* __restrict__ Wm2, const float* __restrict__ bm2)
{
    __shared__ float sW1[16 * 32];
    __shared__ float sB1[32];
    __shared__ float sW2[32];
    __shared__ float sB2;
    int tid = threadIdx.x;
    for (int i = tid; i < 512; i += 256) sW1[i] = Wm1[i];
    if (tid < 32) { sB1[tid] = bm1[tid]; sW2[tid] = Wm2[tid]; }
    if (tid == 0) sB2 = bm2[0];
    __syncthreads();

    int e = blockIdx.x * 256 + tid;
    if (e >= EE) return;

    float a[16];
    const float4* ap = (const float4*)(ea + (size_t)e * 16);
    float4 v0 = ap[0], v1 = ap[1], v2 = ap[2], v3 = ap[3];
    a[0]=v0.x; a[1]=v0.y; a[2]=v0.z; a[3]=v0.w;
    a[4]=v1.x; a[5]=v1.y; a[6]=v1.z; a[7]=v1.w;
    a[8]=v2.x; a[9]=v2.y; a[10]=v2.z; a[11]=v2.w;
    a[12]=v3.x; a[13]=v3.y; a[14]=v3.z; a[15]=v3.w;

    float s = sB2;
    #pragma unroll
    for (int j = 0; j < 32; j++) {
        float h = sB1[j];
        #pragma unroll
        for (int i = 0; i < 16; i++) h = fmaf(a[i], sW1[i * 32 + j], h);
        h = fmaxf(h, 0.f);
        s = fmaf(h, sW2[j], s);
    }
    float ew = (s > 20.f) ? s : log1pf(expf(s));
    g_ew[e] = ew;
    int r = decode_idx(ei[(size_t)estride * e]);
    atomicAdd(&g_deg[r], ew);
    atomicAdd(&g_cnt[r], 1);
}

// ---------------- parallel scan: reduce -> spine -> downsweep ----------------
#define SCAN_NB ((NN + 1023) / 1024)

__global__ __launch_bounds__(1024) void scan_reduce_kernel() {
    __shared__ int sw[32];
    int b = blockIdx.x, tid = threadIdx.x;
    int i = b * 1024 + tid;
    int s = (i < NN) ? g_cnt[i] : 0;
    #pragma unroll
    for (int o = 16; o; o >>= 1) s += __shfl_down_sync(~0u, s, o);
    if ((tid & 31) == 0) sw[tid >> 5] = s;
    __syncthreads();
    if (tid < 32) {
        int t = sw[tid];
        #pragma unroll
        for (int o = 16; o; o >>= 1) t += __shfl_down_sync(~0u, t, o);
        if (tid == 0) g_bsum[b] = t;
    }
}

__global__ __launch_bounds__(64) void scan_spine_kernel() {
    __shared__ int sh[64];
    int tid = threadIdx.x;
    int v = (tid < SCAN_NB) ? g_bsum[tid] : 0;
    sh[tid] = v;
    __syncthreads();
    #pragma unroll
    for (int o = 1; o < 64; o <<= 1) {
        int t = (tid >= o) ? sh[tid - o] : 0;
        __syncthreads();
        sh[tid] += t;
        __syncthreads();
    }
    if (tid < SCAN_NB) g_boff[tid] = sh[tid] - v;
    if (tid == 0) g_offs[NN] = sh[SCAN_NB - 1];
}

__global__ __launch_bounds__(1024) void scan_final_kernel() {
    __shared__ int wsum[32];
    int b = blockIdx.x, tid = threadIdx.x;
    int lane = tid & 31, wd = tid >> 5;
    int i = b * 1024 + tid;
    int v = (i < NN) ? g_cnt[i] : 0;
    int incl = v;
    #pragma unroll
    for (int o = 1; o < 32; o <<= 1) {
        int t = __shfl_up_sync(~0u, incl, o);
        if (lane >= o) incl += t;
    }
    if (lane == 31) wsum[wd] = incl;
    __syncthreads();
    if (tid < 32) {
        int t = wsum[tid];
        int inc = t;
        #pragma unroll
        for (int o = 1; o < 32; o <<= 1) {
            int u = __shfl_up_sync(~0u, inc, o);
            if (tid >= o) inc += u;
        }
        wsum[tid] = inc - t;
    }
    __syncthreads();
    if (i < NN) {
        int excl = incl - v + wsum[wd] + g_boff[b];
        g_offs[i] = excl;
        g_cursor[i] = excl;
        float d = g_deg[i];
        if (d < 0.5f) d += 1.0f;
        g_dinv[i] = 1.0f / d;
    }
}

// ---------------- scatter into CSR ----------------
__global__ __launch_bounds__(256) void scatter_kernel(const unsigned int* __restrict__ ei, int estride) {
    int e = blockIdx.x * 256 + threadIdx.x;
    if (e >= EE) return;
    int r = decode_idx(ei[(size_t)estride * e]);
    int c = decode_idx(ei[(size_t)estride * (EE + e)]);
    int pos = atomicAdd(&g_cursor[r], 1);
    g_ccol[pos] = c;
    g_cw[pos] = g_ew[e] * g_dinv[r];
}

// ---------------- dual GEMM: mma.sync tf32, K-chunk 32, cp.async B ----------------
// CTA: 64 M x 128 N x both branches; grid (782, 2); warp tile 64x32 per branch.
// A packed per chunk: [ks(4)][frag(4)][lane(32)][reg(4)] = 2048 floats (8 KB)
// B per chunk: [n(256)][32] (two permuted 16-groups)      = 8192 floats (32 KB)
#define A_PK  2048
#define B_PK  8192
#define CHBUF (A_PK + B_PK)
#define SMEM_DYN (2 * CHBUF * 4)    // 81920 bytes

template <bool FINAL>
__global__ __launch_bounds__(256, 2) void tc_mma_gemm(
    const float* __restrict__ X,
    const unsigned int* __restrict__ mask,
    const float* __restrict__ bias0, const float* __restrict__ bias1,
    float* __restrict__ Out)
{
    constexpr int K = FINAL ? 512 : 256;
    constexpr int NC = K / 32;
    extern __shared__ float smf[];
    __shared__ float sb0[256], sb1[256], sS[256], sT[256];

    int tid  = threadIdx.x;
    int lane = tid & 31;
    int w    = tid >> 5;
    int wm   = w & 1;          // row half: wm*32
    int wn   = w >> 1;         // col group: wn*32
    int m0   = blockIdx.x * 64;
    int n0   = blockIdx.y * 128;

    sb0[tid] = bias0[tid];
    sb1[tid] = bias1[tid];
    if (FINAL) { sS[tid] = g_ns[tid]; sT[tid] = g_nt[tid]; }
    __syncthreads();

    const float* BT0 = FINAL ? g_Wc0T : g_Wt0T;
    const float* BT1 = FINAL ? g_Wc1T : g_Wt1T;

    float acc[2][2][4][4];     // [branch][mfrag][nfrag][reg]
    #pragma unroll
    for (int b = 0; b < 2; b++)
        #pragma unroll
        for (int f = 0; f < 2; f++)
            #pragma unroll
            for (int g = 0; g < 4; g++)
                #pragma unroll
                for (int r = 0; r < 4; r++) acc[b][f][g][r] = 0.f;

    // A staging decomposition: thread -> row + two float4 k-slots
    const int arow = tid >> 2;            // 0..63
    const int q0   = tid & 3;             // first float4 slot (0..3); second = q0+4
    const int arr  = arow & 15;
    const int afr  = arow >> 4;
    // per-q scatter base:  ks=q>>1, reg=(arr>=8)+2*(q&1), base targets 4 floats at +0,+4,+8,+12
    auto abase_of = [&](int q) {
        int ks  = q >> 1;
        int reg = ((arr >= 8) ? 1 : 0) + ((q & 1) ? 2 : 0);
        return ((ks * 4 + afr) * 32 + (arr & 7) * 4) * 4 + reg;
    };
    const int ab0 = abase_of(q0);
    const int ab1 = abase_of(q0 + 4);

    // B async-copy decomposition: 8 x 16B per thread covers 256 n-rows x 32 floats
    // slot s (0..7): linear idx = tid + s*256 over 2048 float4s; row = idx>>3, j4 = idx&7
    const uint32_t smbase = smem_u32(smf);

    float4 pa0, pa1;
    auto prefA = [&](int c) {
        int m = m0 + arow;
        #pragma unroll
        for (int h = 0; h < 2; h++) {
            int q = q0 + h * 4;
            int kk = c * 32 + q * 4;
            float4 v = make_float4(0.f, 0.f, 0.f, 0.f);
            if (m < NN) {
                if (!FINAL) {
                    v = *(const float4*)&X[(size_t)m * 256 + kk];
                } else if (kk < 256) {
                    float4 g = *(const float4*)&g_agg[(size_t)m * 256 + kk];
                    v.x = fmaf(sS[kk + 0], g.x, sT[kk + 0]);
                    v.y = fmaf(sS[kk + 1], g.y, sT[kk + 1]);
                    v.z = fmaf(sS[kk + 2], g.z, sT[kk + 2]);
                    v.w = fmaf(sS[kk + 3], g.w, sT[kk + 3]);
                } else {
                    v = *(const float4*)&X[(size_t)m * 256 + (kk - 256)];
                }
                v.x = to_tf32(v.x); v.y = to_tf32(v.y);
                v.z = to_tf32(v.z); v.w = to_tf32(v.w);
            }
            if (h == 0) pa0 = v; else pa1 = v;
        }
    };
    auto storeA = [&](int buf) {
        float* sA = smf + buf * CHBUF;
        sA[ab0 + 0]  = pa0.x; sA[ab0 + 4]  = pa0.y;
        sA[ab0 + 8]  = pa0.z; sA[ab0 + 12] = pa0.w;
        sA[ab1 + 0]  = pa1.x; sA[ab1 + 4]  = pa1.y;
        sA[ab1 + 8]  = pa1.z; sA[ab1 + 12] = pa1.w;
    };
    auto asyncB = [&](int c, int buf) {
        uint32_t dstb = smbase + (buf * CHBUF + A_PK) * 4;
        #pragma unroll
        for (int s = 0; s < 8; s++) {
            int idx = tid + s * 256;          // over 2048 float4
            int nr = idx >> 3, j4 = idx & 7;
            int br = nr >> 7;
            int nn = (nr & 127) + n0;
            const float* src = (br ? BT1 : BT0) + (size_t)nn * K + c * 32 + j4 * 4;
            CP_ASYNC16(dstb + (uint32_t)(nr * 32 + j4 * 4) * 4, src);
        }
        CP_COMMIT();
    };
    auto compute = [&](int buf) {
        const float* sA = smf + buf * CHBUF;
        const float* sB = sA + A_PK;
        #pragma unroll
        for (int grp = 0; grp < 2; grp++) {
            uint32_t a[2][2][4];   // [ks within grp][mfrag][reg]
            #pragma unroll
            for (int kh = 0; kh < 2; kh++)
                #pragma unroll
                for (int f = 0; f < 2; f++) {
                    int ks = grp * 2 + kh;
                    float4 av = *(const float4*)&sA[((ks * 4 + (wm * 2 + f)) * 32 + lane) * 4];
                    a[kh][f][0] = fbits(av.x); a[kh][f][1] = fbits(av.y);
                    a[kh][f][2] = fbits(av.z); a[kh][f][3] = fbits(av.w);
                }
            #pragma unroll
            for (int br = 0; br < 2; br++) {
                #pragma unroll
                for (int g = 0; g < 4; g++) {
                    int n = br * 128 + wn * 32 + g * 8 + (lane >> 2);
                    float4 bb = *(const float4*)&sB[n * 32 + grp * 16 + (lane & 3) * 4];
                    uint32_t b00 = fbits(bb.x), b01 = fbits(bb.y);
                    uint32_t b10 = fbits(bb.z), b11 = fbits(bb.w);
                    MMA_TF32(acc[br][0][g], a[0][0], b00, b01);
                    MMA_TF32(acc[br][1][g], a[0][1], b00, b01);
                    MMA_TF32(acc[br][0][g], a[1][0], b10, b11);
                    MMA_TF32(acc[br][1][g], a[1][1], b10, b11);
                }
            }
        }
    };

    // pipeline: stage chunk0, then per-iter: wait B(c) -> sync -> stage(c+1) -> compute(c)
    prefA(0);
    asyncB(0, 0);
    storeA(0);
    for (int c = 0; c < NC; c++) {
        CP_WAIT0();
        __syncthreads();            // all compute(c-1) done; B(c)+A(c) visible
        if (c + 1 < NC) {
            prefA(c + 1);
            asyncB(c + 1, (c + 1) & 1);   // into free buffer, overlaps compute below
            storeA((c + 1) & 1);
        }
        compute(c & 1);
    }

    // ---- epilogue: bias (+relu) + register-local masked mix ----
    float* dst = FINAL ? Out : g_xm;
    #pragma unroll
    for (int f = 0; f < 2; f++) {
        int r0 = m0 + wm * 32 + f * 16 + (lane >> 2);
        int r1 = r0 + 8;
        unsigned mk0 = (r0 < NN) ? mask[r0] : 0u;
        unsigned mk1 = (r1 < NN) ? mask[r1] : 0u;
        float za0 = mk0 ? (1.f - ZMIX) : ZMIX, zb0 = mk0 ? ZMIX : (1.f - ZMIX);
        float za1 = mk1 ? (1.f - ZMIX) : ZMIX, zb1 = mk1 ? ZMIX : (1.f - ZMIX);
        #pragma unroll
        for (int g = 0; g < 4; g++) {
            int col = n0 + wn * 32 + g * 8 + (lane & 3) * 2;
            float v00 = acc[0][f][g][0] + sb0[col];
            float v01 = acc[0][f][g][1] + sb0[col + 1];
            float v10 = acc[1][f][g][0] + sb1[col];
            float v11 = acc[1][f][g][1] + sb1[col + 1];
            float u00 = acc[0][f][g][2] + sb0[col];
            float u01 = acc[0][f][g][3] + sb0[col + 1];
            float u10 = acc[1][f][g][2] + sb1[col];
            float u11 = acc[1][f][g][3] + sb1[col + 1];
            if (!FINAL) {
                v00 = fmaxf(v00, 0.f); v01 = fmaxf(v01, 0.f);
                v10 = fmaxf(v10, 0.f); v11 = fmaxf(v11, 0.f);
                u00 = fmaxf(u00, 0.f); u01 = fmaxf(u01, 0.f);
                u10 = fmaxf(u10, 0.f); u11 = fmaxf(u11, 0.f);
            }
            if (r0 < NN) {
                float2 o = make_float2(za0 * v00 + zb0 * v10, za0 * v01 + zb0 * v11);
                *(float2*)&dst[(size_t)r0 * 256 + col] = o;
            }
            if (r1 < NN) {
                float2 o = make_float2(za1 * u00 + zb1 * u10, za1 * u01 + zb1 * u11);
                *(float2*)&dst[(size_t)r1 * 256 + col] = o;
            }
        }
    }
}

// ---------------- aggregation: one block per row, gather over CSR ----------------
__global__ __launch_bounds__(256) void agg_kernel() {
    int r = blockIdx.x;
    int d = threadIdx.x;
    int beg = g_offs[r], end = g_offs[r + 1];
    float acc = 0.f;
    for (int j = beg; j < end; j++) {
        int c = g_ccol[j];
        float w = g_cw[j];
        acc = fmaf(w, g_xm[(size_t)c * DOUTC + d], acc);
    }
    g_agg[(size_t)r * DOUTC + d] = acc;
}

// ---------------- column stats ----------------
__global__ __launch_bounds__(256) void colstats_kernel() {
    int d = threadIdx.x;
    float s = 0.f, s2 = 0.f;
    for (int r = blockIdx.x; r < NN; r += gridDim.x) {
        float v = g_agg[(size_t)r * DOUTC + d];
        s += v;
        s2 = fmaf(v, v, s2);
    }
    atomicAdd(&g_colsum[d], s);
    atomicAdd(&g_colsq[d], s2);
}

// ---------------- GraphNorm params ----------------
__global__ __launch_bounds__(256) void normparams_kernel(
    const float* __restrict__ gn_w, const float* __restrict__ gn_b,
    const float* __restrict__ gn_alpha)
{
    int d = threadIdx.x;
    float m = g_colsum[d] * (1.0f / NN);
    float a = gn_alpha[d];
    float var = g_colsq[d] * (1.0f / NN) + m * m * (a * a - 2.f * a);
    float rstd = rsqrtf(var + EPSGN);
    float s = gn_w[d] * rstd;
    g_ns[d] = s;
    g_nt[d] = gn_b[d] - s * a * m;
}

// ---------------- launch ----------------
extern "C" void kernel_launch(void* const* d_in, const int* in_sizes, int n_in,
                              void* d_out, int out_size)
{
    const float*        x      = (const float*)d_in[0];
    const unsigned int* ei     = (const unsigned int*)d_in[1];
    const unsigned int* mask   = (const unsigned int*)d_in[3];
    const float*        ea     = (const float*)d_in[4];
    const float*        Wt0    = (const float*)d_in[5];
    const float*        bt0    = (const float*)d_in[6];
    const float*        Wt1    = (const float*)d_in[7];
    const float*        bt1    = (const float*)d_in[8];
    const float*        Wc0    = (const float*)d_in[9];
    const float*        bc0    = (const float*)d_in[10];
    const float*        Wc1    = (const float*)d_in[11];
    const float*        bc1    = (const float*)d_in[12];
    const float*        gn_w   = (const float*)d_in[13];
    const float*        gn_b   = (const float*)d_in[14];
    const float*        gn_a   = (const float*)d_in[15];
    const float*        Wm1    = (const float*)d_in[16];
    const float*        bm1    = (const float*)d_in[17];
    const float*        Wm2    = (const float*)d_in[18];
    const float*        bm2    = (const float*)d_in[19];
    float*              out    = (float*)d_out;

    int estride = (in_sizes[1] >= 4 * EE) ? 2 : 1;

    cudaFuncSetAttribute(tc_mma_gemm<false>,
                         cudaFuncAttributeMaxDynamicSharedMemorySize, SMEM_DYN);
    cudaFuncSetAttribute(tc_mma_gemm<true>,
                         cudaFuncAttributeMaxDynamicSharedMemorySize, SMEM_DYN);

    dim3 ggrid((NN + 63) / 64, 2);

    // GEMM1 placed at launch idx 3 so ncu's fixed-skip capture finally profiles a GEMM.
    init_kernel<<<256, 256>>>();
    prep_weights_kernel<<<64, 256>>>(Wt0, 256, 0);
    prep_weights_kernel<<<64, 256>>>(Wt1, 256, 1);
    // xm = mix(mask, relu(x@Wt1+bt1), relu(x@Wt0+bt0)) -> g_xm
    tc_mma_gemm<false><<<ggrid, 256, SMEM_DYN>>>(x, mask, bt0, bt1, nullptr);
    prep_weights_kernel<<<128, 256>>>(Wc0, 512, 2);
    prep_weights_kernel<<<128, 256>>>(Wc1, 512, 3);
    edge_mlp_kernel<<<(EE + 255) / 256, 256>>>(ea, ei, estride, Wm1, bm1, Wm2, bm2);
    scan_reduce_kernel<<<SCAN_NB, 1024>>>();
    scan_spine_kernel<<<1, 64>>>();
    scan_final_kernel<<<SCAN_NB, 1024>>>();
    scatter_kernel<<<(EE + 255) / 256, 256>>>(ei, estride);

    agg_kernel<<<NN, 256>>>();
    colstats_kernel<<<512, 256>>>();
    normparams_kernel<<<1, 256>>>(gn_w, gn_b, gn_a);

    // out = mix(mask, xc@Wc1+bc1, xc@Wc0+bc0), xc = [norm(agg) | x]
    tc_mma_gemm<true><<<ggrid, 256, SMEM_DYN>>>(x, mask, bc0, bc1, out);
}

// round 16
// speedup vs baseline: 1.0878x; 1.0878x over previous
#include <cuda_runtime.h>
#include <math.h>
#include <cstdint>

#define NN    50000
#define EE    800000
#define DIN   256
#define DOUTC 256
#define ZMIX  0.8f
#define EPSGN 1e-5f

// ---------------- scratch (static device globals; no allocation) ----------------
__device__ float g_ew[EE];
__device__ float g_deg[NN];
__device__ float g_dinv[NN];
__device__ int   g_cnt[NN];
__device__ int   g_offs[NN + 1];
__device__ int   g_cursor[NN];
__device__ int   g_ccol[EE];
__device__ float g_cw[EE];
__device__ float g_xm[NN * DOUTC];
__device__ float g_agg[NN * DOUTC];
__device__ float g_colsum[DOUTC];
__device__ float g_colsq[DOUTC];
__device__ float g_ns[DOUTC];
__device__ float g_nt[DOUTC];
__device__ int   g_bsum[64];
__device__ int   g_boff[64];

// weights: [n][K], RNA-rounded tf32, each 16-k group permuted so word (c*4+q)
// holds W[k_local=c+4q][n] => one LDS.128 per B fragment pair on compute side.
__device__ float g_Wt0T[256 * 256];
__device__ float g_Wt1T[256 * 256];
__device__ float g_Wc0T[256 * 512];
__device__ float g_Wc1T[256 * 512];

__device__ __forceinline__ float to_tf32(float x) {
    float r;
    asm("cvt.rna.tf32.f32 %0, %1;" : "=f"(r) : "f"(x));
    return r;
}
__device__ __forceinline__ uint32_t fbits(float x) { return __float_as_uint(x); }
__device__ __forceinline__ uint32_t smem_u32(const void* p) {
    uint32_t a;
    asm("{ .reg .u64 t; cvta.to.shared.u64 t, %1; cvt.u32.u64 %0, t; }" : "=r"(a) : "l"(p));
    return a;
}

#define MMA_TF32(C, A, B0, B1) \
    asm volatile("mma.sync.aligned.m16n8k8.row.col.f32.tf32.tf32.f32 " \
        "{%0,%1,%2,%3}, {%4,%5,%6,%7}, {%8,%9}, {%0,%1,%2,%3};" \
        : "+f"((C)[0]), "+f"((C)[1]), "+f"((C)[2]), "+f"((C)[3]) \
        : "r"((A)[0]), "r"((A)[1]), "r"((A)[2]), "r"((A)[3]), "r"(B0), "r"(B1))

#define LDMATRIX_X4(r0, r1, r2, r3, addr) \
    asm volatile("ldmatrix.sync.aligned.m8n8.x4.shared.b16 {%0,%1,%2,%3}, [%4];" \
        : "=r"(r0), "=r"(r1), "=r"(r2), "=r"(r3) : "r"(addr))

__device__ __forceinline__ int decode_idx(unsigned int w) {
    int v = (w >= 0x3F000000u) ? (int)__uint_as_float(w) : (int)w;
    v = v < 0 ? 0 : (v >= NN ? NN - 1 : v);
    return v;
}

// ---------------- init ----------------
__global__ void init_kernel() {
    int i = blockIdx.x * blockDim.x + threadIdx.x;
    int stride = gridDim.x * blockDim.x;
    for (int j = i; j < NN; j += stride) { g_deg[j] = 0.f; g_cnt[j] = 0; }
    for (int j = i; j < DOUTC; j += stride) { g_colsum[j] = 0.f; g_colsq[j] = 0.f; }
}

// ---------------- weight prep: [K,N] -> [n][K] permuted-16-group, RNA tf32 ----------------
__global__ __launch_bounds__(256) void prep_weights_kernel(const float* __restrict__ W, int K, int sel) {
    float* dst = (sel == 0) ? g_Wt0T : (sel == 1) ? g_Wt1T : (sel == 2) ? g_Wc0T : g_Wc1T;
    int idx = blockIdx.x * 256 + threadIdx.x;   // over K*64 float4s
    if (idx >= K * 64) return;
    int k = idx >> 6;
    int n4 = idx & 63;
    float4 v = ((const float4*)W)[idx];         // W[k][4*n4 .. 4*n4+3]
    int kl = k & 15;
    int off = (k >> 4) * 16 + (kl & 3) * 4 + (kl >> 2);
    float vv[4] = {v.x, v.y, v.z, v.w};
    #pragma unroll
    for (int j = 0; j < 4; j++)
        dst[(size_t)(n4 * 4 + j) * K + off] = to_tf32(vv[j]);
}

// ---------------- edge MLP ----------------
__global__ __launch_bounds__(256) void edge_mlp_kernel(
    const float* __restrict__ ea, const unsigned int* __restrict__ ei, int estride,
    const float* __restrict__ Wm1, const float* __restrict__ bm1,
    const float* __restrict__ Wm2, const float* __restrict__ bm2)
{
    __shared__ float sW1[16 * 32];
    __shared__ float sB1[32];
    __shared__ float sW2[32];
    __shared__ float sB2;
    int tid = threadIdx.x;
    for (int i = tid; i < 512; i += 256) sW1[i] = Wm1[i];
    if (tid < 32) { sB1[tid] = bm1[tid]; sW2[tid] = Wm2[tid]; }
    if (tid == 0) sB2 = bm2[0];
    __syncthreads();

    int e = blockIdx.x * 256 + tid;
    if (e >= EE) return;

    float a[16];
    const float4* ap = (const float4*)(ea + (size_t)e * 16);
    float4 v0 = ap[0], v1 = ap[1], v2 = ap[2], v3 = ap[3];
    a[0]=v0.x; a[1]=v0.y; a[2]=v0.z; a[3]=v0.w;
    a[4]=v1.x; a[5]=v1.y; a[6]=v1.z; a[7]=v1.w;
    a[8]=v2.x; a[9]=v2.y; a[10]=v2.z; a[11]=v2.w;
    a[12]=v3.x; a[13]=v3.y; a[14]=v3.z; a[15]=v3.w;

    float s = sB2;
    #pragma unroll
    for (int j = 0; j < 32; j++) {
        float h = sB1[j];
        #pragma unroll
        for (int i = 0; i < 16; i++) h = fmaf(a[i], sW1[i * 32 + j], h);
        h = fmaxf(h, 0.f);
        s = fmaf(h, sW2[j], s);
    }
    float ew = (s > 20.f) ? s : log1pf(expf(s));
    g_ew[e] = ew;
    int r = decode_idx(ei[(size_t)estride * e]);
    atomicAdd(&g_deg[r], ew);
    atomicAdd(&g_cnt[r], 1);
}

// ---------------- parallel scan: reduce -> spine -> downsweep ----------------
#define SCAN_NB ((NN + 1023) / 1024)

__global__ __launch_bounds__(1024) void scan_reduce_kernel() {
    __shared__ int sw[32];
    int b = blockIdx.x, tid = threadIdx.x;
    int i = b * 1024 + tid;
    int s = (i < NN) ? g_cnt[i] : 0;
    #pragma unroll
    for (int o = 16; o; o >>= 1) s += __shfl_down_sync(~0u, s, o);
    if ((tid & 31) == 0) sw[tid >> 5] = s;
    __syncthreads();
    if (tid < 32) {
        int t = sw[tid];
        #pragma unroll
        for (int o = 16; o; o >>= 1) t += __shfl_down_sync(~0u, t, o);
        if (tid == 0) g_bsum[b] = t;
    }
}

__global__ __launch_bounds__(64) void scan_spine_kernel() {
    __shared__ int sh[64];
    int tid = threadIdx.x;
    int v = (tid < SCAN_NB) ? g_bsum[tid] : 0;
    sh[tid] = v;
    __syncthreads();
    #pragma unroll
    for (int o = 1; o < 64; o <<= 1) {
        int t = (tid >= o) ? sh[tid - o] : 0;
        __syncthreads();
        sh[tid] += t;
        __syncthreads();
    }
    if (tid < SCAN_NB) g_boff[tid] = sh[tid] - v;
    if (tid == 0) g_offs[NN] = sh[SCAN_NB - 1];
}

__global__ __launch_bounds__(1024) void scan_final_kernel() {
    __shared__ int wsum[32];
    int b = blockIdx.x, tid = threadIdx.x;
    int lane = tid & 31, wd = tid >> 5;
    int i = b * 1024 + tid;
    int v = (i < NN) ? g_cnt[i] : 0;
    int incl = v;
    #pragma unroll
    for (int o = 1; o < 32; o <<= 1) {
        int t = __shfl_up_sync(~0u, incl, o);
        if (lane >= o) incl += t;
    }
    if (lane == 31) wsum[wd] = incl;
    __syncthreads();
    if (tid < 32) {
        int t = wsum[tid];
        int inc = t;
        #pragma unroll
        for (int o = 1; o < 32; o <<= 1) {
            int u = __shfl_up_sync(~0u, inc, o);
            if (tid >= o) inc += u;
        }
        wsum[tid] = inc - t;
    }
    __syncthreads();
    if (i < NN) {
        int excl = incl - v + wsum[wd] + g_boff[b];
        g_offs[i] = excl;
        g_cursor[i] = excl;
        float d = g_deg[i];
        if (d < 0.5f) d += 1.0f;
        g_dinv[i] = 1.0f / d;
    }
}

// ---------------- scatter into CSR ----------------
__global__ __launch_bounds__(256) void scatter_kernel(const unsigned int* __restrict__ ei, int estride) {
    int e = blockIdx.x * 256 + threadIdx.x;
    if (e >= EE) return;
    int r = decode_idx(ei[(size_t)estride * e]);
    int c = decode_idx(ei[(size_t)estride * (EE + e)]);
    int pos = atomicAdd(&g_cursor[r], 1);
    g_ccol[pos] = c;
    g_cw[pos] = g_ew[e] * g_dinv[r];
}

// ---------------- dual GEMM: mma.sync tf32, ldmatrix A, 16-K chunks ----------------
// CTA: 64 M x 128 N x both branches; grid (782, 2); warp tile 64x32 per branch.
// A per chunk: row-major [64 rows][20 floats] (pad->conflict-free LDSM) = 1280 floats
// B per chunk: [n(256)][16] permuted word order                         = 4096 floats
#define APITCH 20
#define A_PK  (64 * APITCH)
#define B_PK  4096
#define CHBUF (A_PK + B_PK)
#define SMEM_DYN (2 * CHBUF * 4)    // 43008 bytes

template <bool FINAL>
__global__ __launch_bounds__(256, 2) void tc_mma_gemm(
    const float* __restrict__ X,
    const unsigned int* __restrict__ mask,
    const float* __restrict__ bias0, const float* __restrict__ bias1,
    float* __restrict__ Out)
{
    constexpr int K = FINAL ? 512 : 256;
    constexpr int NC = K / 16;
    extern __shared__ float smf[];
    __shared__ float sb0[256], sb1[256], sS[256], sT[256];

    int tid  = threadIdx.x;
    int lane = tid & 31;
    int w    = tid >> 5;
    int wm   = w & 1;          // row half: wm*32
    int wn   = w >> 1;         // col group: wn*32
    int m0   = blockIdx.x * 64;
    int n0   = blockIdx.y * 128;

    sb0[tid] = bias0[tid];
    sb1[tid] = bias1[tid];
    if (FINAL) { sS[tid] = g_ns[tid]; sT[tid] = g_nt[tid]; }
    __syncthreads();

    const float* BT0 = FINAL ? g_Wc0T : g_Wt0T;
    const float* BT1 = FINAL ? g_Wc1T : g_Wt1T;
    const uint32_t smbase = smem_u32(smf);

    float acc[2][2][4][4];     // [branch][mfrag][nfrag][reg]
    #pragma unroll
    for (int b = 0; b < 2; b++)
        #pragma unroll
        for (int f = 0; f < 2; f++)
            #pragma unroll
            for (int g = 0; g < 4; g++)
                #pragma unroll
                for (int r = 0; r < 4; r++) acc[b][f][g][r] = 0.f;

    // A staging: thread -> (row, float4 slot); plain row-major store
    const int arow = tid >> 2;            // 0..63
    const int q    = tid & 3;             // float4 k-slot

    // ldmatrix per-lane source row/k within the warp's A view
    const int ltile = lane >> 3;                       // 0..3
    const int lrow  = ((ltile & 1) << 3) + (lane & 7); // row within 16-row frag
    const int lk    = (ltile >> 1) << 2;               // 0 or 4

    float4 pa;
    float4 pb[4];
    auto prefetch = [&](int c) {
        // A: 64 rows x 16 k, 1 float4/thread (tf32-rounded, GraphNorm fused if FINAL)
        {
            int m = m0 + arow;
            int kk = c * 16 + q * 4;
            float4 v = make_float4(0.f, 0.f, 0.f, 0.f);
            if (m < NN) {
                if (!FINAL) {
                    v = *(const float4*)&X[(size_t)m * 256 + kk];
                } else if (kk < 256) {
                    float4 g = *(const float4*)&g_agg[(size_t)m * 256 + kk];
                    v.x = fmaf(sS[kk + 0], g.x, sT[kk + 0]);
                    v.y = fmaf(sS[kk + 1], g.y, sT[kk + 1]);
                    v.z = fmaf(sS[kk + 2], g.z, sT[kk + 2]);
                    v.w = fmaf(sS[kk + 3], g.w, sT[kk + 3]);
                } else {
                    v = *(const float4*)&X[(size_t)m * 256 + (kk - 256)];
                }
                v.x = to_tf32(v.x); v.y = to_tf32(v.y);
                v.z = to_tf32(v.z); v.w = to_tf32(v.w);
            }
            pa = v;
        }
        // B: straight float4 copy of permuted weights (256 n-rows x 4 quads)
        #pragma unroll
        for (int i = 0; i < 4; i++) {
            int idx = tid + i * 256;
            int nr = idx >> 2, j4 = idx & 3;
            int br = nr >> 7;
            int nn = (nr & 127) + n0;
            const float* src = br ? BT1 : BT0;
            pb[i] = *(const float4*)&src[(size_t)nn * K + c * 16 + j4 * 4];
        }
    };
    auto stores = [&](int buf) {
        float* sA = smf + buf * CHBUF;
        float* sB = sA + A_PK;
        *(float4*)&sA[arow * APITCH + q * 4] = pa;       // one STS.128, ~2-way worst
        #pragma unroll
        for (int i = 0; i < 4; i++) {
            int idx = tid + i * 256;
            int nr = idx >> 2, j4 = idx & 3;
            *(float4*)&sB[nr * 16 + j4 * 4] = pb[i];
        }
    };
    auto compute = [&](int buf) {
        uint32_t abase = smbase + (uint32_t)(buf * CHBUF) * 4;
        const float* sB = smf + buf * CHBUF + A_PK;
        // A fragments via ldmatrix.x4 (one per (ks, mfrag)), conflict-free
        uint32_t a[2][2][4];   // [ks][mfrag][reg]
        #pragma unroll
        for (int ks = 0; ks < 2; ks++)
            #pragma unroll
            for (int f = 0; f < 2; f++) {
                int row = wm * 32 + f * 16 + lrow;
                uint32_t addr = abase + (uint32_t)(row * APITCH + ks * 8 + lk) * 4;
                LDMATRIX_X4(a[ks][f][0], a[ks][f][1], a[ks][f][2], a[ks][f][3], addr);
            }
        #pragma unroll
        for (int br = 0; br < 2; br++) {
            #pragma unroll
            for (int g = 0; g < 4; g++) {
                int n = br * 128 + wn * 32 + g * 8 + (lane >> 2);
                float4 bb = *(const float4*)&sB[n * 16 + (lane & 3) * 4];
                uint32_t b00 = fbits(bb.x), b01 = fbits(bb.y);
                uint32_t b10 = fbits(bb.z), b11 = fbits(bb.w);
                MMA_TF32(acc[br][0][g], a[0][0], b00, b01);
                MMA_TF32(acc[br][1][g], a[0][1], b00, b01);
                MMA_TF32(acc[br][0][g], a[1][0], b10, b11);
                MMA_TF32(acc[br][1][g], a[1][1], b10, b11);
            }
        }
    };

    prefetch(0);
    stores(0);
    for (int c = 0; c < NC; c++) {
        __syncthreads();
        if (c + 1 < NC) prefetch(c + 1);
        compute(c & 1);
        if (c + 1 < NC) stores((c + 1) & 1);
    }

    // ---- epilogue: bias (+relu) + register-local masked mix ----
    float* dst = FINAL ? Out : g_xm;
    #pragma unroll
    for (int f = 0; f < 2; f++) {
        int r0 = m0 + wm * 32 + f * 16 + (lane >> 2);
        int r1 = r0 + 8;
        unsigned mk0 = (r0 < NN) ? mask[r0] : 0u;
        unsigned mk1 = (r1 < NN) ? mask[r1] : 0u;
        float za0 = mk0 ? (1.f - ZMIX) : ZMIX, zb0 = mk0 ? ZMIX : (1.f - ZMIX);
        float za1 = mk1 ? (1.f - ZMIX) : ZMIX, zb1 = mk1 ? ZMIX : (1.f - ZMIX);
        #pragma unroll
        for (int g = 0; g < 4; g++) {
            int col = n0 + wn * 32 + g * 8 + (lane & 3) * 2;
            float v00 = acc[0][f][g][0] + sb0[col];
            float v01 = acc[0][f][g][1] + sb0[col + 1];
            float v10 = acc[1][f][g][0] + sb1[col];
            float v11 = acc[1][f][g][1] + sb1[col + 1];
            float u00 = acc[0][f][g][2] + sb0[col];
            float u01 = acc[0][f][g][3] + sb0[col + 1];
            float u10 = acc[1][f][g][2] + sb1[col];
            float u11 = acc[1][f][g][3] + sb1[col + 1];
            if (!FINAL) {
                v00 = fmaxf(v00, 0.f); v01 = fmaxf(v01, 0.f);
                v10 = fmaxf(v10, 0.f); v11 = fmaxf(v11, 0.f);
                u00 = fmaxf(u00, 0.f); u01 = fmaxf(u01, 0.f);
                u10 = fmaxf(u10, 0.f); u11 = fmaxf(u11, 0.f);
            }
            if (r0 < NN) {
                float2 o = make_float2(za0 * v00 + zb0 * v10, za0 * v01 + zb0 * v11);
                *(float2*)&dst[(size_t)r0 * 256 + col] = o;
            }
            if (r1 < NN) {
                float2 o = make_float2(za1 * u00 + zb1 * u10, za1 * u01 + zb1 * u11);
                *(float2*)&dst[(size_t)r1 * 256 + col] = o;
            }
        }
    }
}

// ---------------- aggregation: one block per row, gather over CSR ----------------
__global__ __launch_bounds__(256) void agg_kernel() {
    int r = blockIdx.x;
    int d = threadIdx.x;
    int beg = g_offs[r], end = g_offs[r + 1];
    float acc = 0.f;
    for (int j = beg; j < end; j++) {
        int c = g_ccol[j];
        float w = g_cw[j];
        acc = fmaf(w, g_xm[(size_t)c * DOUTC + d], acc);
    }
    g_agg[(size_t)r * DOUTC + d] = acc;
}

// ---------------- column stats ----------------
__global__ __launch_bounds__(256) void colstats_kernel() {
    int d = threadIdx.x;
    float s = 0.f, s2 = 0.f;
    for (int r = blockIdx.x; r < NN; r += gridDim.x) {
        float v = g_agg[(size_t)r * DOUTC + d];
        s += v;
        s2 = fmaf(v, v, s2);
    }
    atomicAdd(&g_colsum[d], s);
    atomicAdd(&g_colsq[d], s2);
}

// ---------------- GraphNorm params ----------------
__global__ __launch_bounds__(256) void normparams_kernel(
    const float* __restrict__ gn_w, const float* __restrict__ gn_b,
    const float* __restrict__ gn_alpha)
{
    int d = threadIdx.x;
    float m = g_colsum[d] * (1.0f / NN);
    float a = gn_alpha[d];
    float var = g_colsq[d] * (1.0f / NN) + m * m * (a * a - 2.f * a);
    float rstd = rsqrtf(var + EPSGN);
    float s = gn_w[d] * rstd;
    g_ns[d] = s;
    g_nt[d] = gn_b[d] - s * a * m;
}

// ---------------- launch ----------------
extern "C" void kernel_launch(void* const* d_in, const int* in_sizes, int n_in,
                              void* d_out, int out_size)
{
    const float*        x      = (const float*)d_in[0];
    const unsigned int* ei     = (const unsigned int*)d_in[1];
    const unsigned int* mask   = (const unsigned int*)d_in[3];
    const float*        ea     = (const float*)d_in[4];
    const float*        Wt0    = (const float*)d_in[5];
    const float*        bt0    = (const float*)d_in[6];
    const float*        Wt1    = (const float*)d_in[7];
    const float*        bt1    = (const float*)d_in[8];
    const float*        Wc0    = (const float*)d_in[9];
    const float*        bc0    = (const float*)d_in[10];
    const float*        Wc1    = (const float*)d_in[11];
    const float*        bc1    = (const float*)d_in[12];
    const float*        gn_w   = (const float*)d_in[13];
    const float*        gn_b   = (const float*)d_in[14];
    const float*        gn_a   = (const float*)d_in[15];
    const float*        Wm1    = (const float*)d_in[16];
    const float*        bm1    = (const float*)d_in[17];
    const float*        Wm2    = (const float*)d_in[18];
    const float*        bm2    = (const float*)d_in[19];
    float*              out    = (float*)d_out;

    int estride = (in_sizes[1] >= 4 * EE) ? 2 : 1;

    cudaFuncSetAttribute(tc_mma_gemm<false>,
                         cudaFuncAttributeMaxDynamicSharedMemorySize, SMEM_DYN);
    cudaFuncSetAttribute(tc_mma_gemm<true>,
                         cudaFuncAttributeMaxDynamicSharedMemorySize, SMEM_DYN);

    dim3 ggrid((NN + 63) / 64, 2);

    // GEMM1 at launch idx 3 so ncu's fixed-skip capture profiles a GEMM.
    init_kernel<<<256, 256>>>();
    prep_weights_kernel<<<64, 256>>>(Wt0, 256, 0);
    prep_weights_kernel<<<64, 256>>>(Wt1, 256, 1);
    // xm = mix(mask, relu(x@Wt1+bt1), relu(x@Wt0+bt0)) -> g_xm
    tc_mma_gemm<false><<<ggrid, 256, SMEM_DYN>>>(x, mask, bt0, bt1, nullptr);
    prep_weights_kernel<<<128, 256>>>(Wc0, 512, 2);
    prep_weights_kernel<<<128, 256>>>(Wc1, 512, 3);
    edge_mlp_kernel<<<(EE + 255) / 256, 256>>>(ea, ei, estride, Wm1, bm1, Wm2, bm2);
    scan_reduce_kernel<<<SCAN_NB, 1024>>>();
    scan_spine_kernel<<<1, 64>>>();
    scan_final_kernel<<<SCAN_NB, 1024>>>();
    scatter_kernel<<<(EE + 255) / 256, 256>>>(ei, estride);

    agg_kernel<<<NN, 256>>>();
    colstats_kernel<<<512, 256>>>();
    normparams_kernel<<<1, 256>>>(gn_w, gn_b, gn_a);

    // out = mix(mask, xc@Wc1+bc1, xc@Wc0+bc0), xc = [norm(agg) | x]
    tc_mma_gemm<true><<<ggrid, 256, SMEM_DYN>>>(x, mask, bc0, bc1, out);
}

// round 17
// speedup vs baseline: 1.3060x; 1.2006x over previous
#include <cuda_runtime.h>
#include <math.h>
#include <cstdint>

#define NN    50000
#define EE    800000
#define DIN   256
#define DOUTC 256
#define ZMIX  0.8f
#define EPSGN 1e-5f

// ---------------- scratch (static device globals; no allocation) ----------------
__device__ float g_ew[EE];
__device__ float g_deg[NN];
__device__ float g_dinv[NN];
__device__ int   g_cnt[NN];
__device__ int   g_offs[NN + 1];
__device__ int   g_cursor[NN];
__device__ int   g_ccol[EE];
__device__ float g_cw[EE];
__device__ float g_xm[NN * DOUTC];
__device__ float g_agg[NN * DOUTC];
__device__ float g_colsum[DOUTC];
__device__ float g_colsq[DOUTC];
__device__ float g_ns[DOUTC];
__device__ float g_nt[DOUTC];
__device__ int   g_bsum[64];
__device__ int   g_boff[64];

// pre-rounded A operands (padded 64 rows so OOB cp.async of the last tile is safe)
__device__ float g_xr[(NN + 64) * 256];   // rna(x)
__device__ float g_ar[(NN + 64) * 256];   // rna(ns*agg + nt)

// weights: [n][K], RNA-rounded tf32, each 16-k group permuted so word (c*4+q)
// holds W[k_local=c+4q][n] => one LDS.128 per B fragment pair on compute side.
__device__ float g_Wt0T[256 * 256];
__device__ float g_Wt1T[256 * 256];
__device__ float g_Wc0T[256 * 512];
__device__ float g_Wc1T[256 * 512];

__device__ __forceinline__ float to_tf32(float x) {
    float r;
    asm("cvt.rna.tf32.f32 %0, %1;" : "=f"(r) : "f"(x));
    return r;
}
__device__ __forceinline__ uint32_t fbits(float x) { return __float_as_uint(x); }
__device__ __forceinline__ uint32_t smem_u32(const void* p) {
    uint32_t a;
    asm("{ .reg .u64 t; cvta.to.shared.u64 t, %1; cvt.u32.u64 %0, t; }" : "=r"(a) : "l"(p));
    return a;
}

#define CP_ASYNC16(dst_u32, src_ptr) \
    asm volatile("cp.async.cg.shared.global [%0], [%1], 16;" :: "r"(dst_u32), "l"(src_ptr))
#define CP_COMMIT()  asm volatile("cp.async.commit_group;" ::: "memory")
#define CP_WAIT2()   asm volatile("cp.async.wait_group 2;" ::: "memory")

#define MMA_TF32(C, A, B0, B1) \
    asm volatile("mma.sync.aligned.m16n8k8.row.col.f32.tf32.tf32.f32 " \
        "{%0,%1,%2,%3}, {%4,%5,%6,%7}, {%8,%9}, {%0,%1,%2,%3};" \
        : "+f"((C)[0]), "+f"((C)[1]), "+f"((C)[2]), "+f"((C)[3]) \
        : "r"((A)[0]), "r"((A)[1]), "r"((A)[2]), "r"((A)[3]), "r"(B0), "r"(B1))

#define LDMATRIX_X4(r0, r1, r2, r3, addr) \
    asm volatile("ldmatrix.sync.aligned.m8n8.x4.shared.b16 {%0,%1,%2,%3}, [%4];" \
        : "=r"(r0), "=r"(r1), "=r"(r2), "=r"(r3) : "r"(addr))

__device__ __forceinline__ int decode_idx(unsigned int w) {
    int v = (w >= 0x3F000000u) ? (int)__uint_as_float(w) : (int)w;
    v = v < 0 ? 0 : (v >= NN ? NN - 1 : v);
    return v;
}

// ---------------- init ----------------
__global__ void init_kernel() {
    int i = blockIdx.x * blockDim.x + threadIdx.x;
    int stride = gridDim.x * blockDim.x;
    for (int j = i; j < NN; j += stride) { g_deg[j] = 0.f; g_cnt[j] = 0; }
    for (int j = i; j < DOUTC; j += stride) { g_colsum[j] = 0.f; g_colsq[j] = 0.f; }
}

// ---------------- prep x: g_xr = rna(x) ----------------
__global__ __launch_bounds__(256) void prep_x_kernel(const float* __restrict__ X) {
    int i = blockIdx.x * 256 + threadIdx.x;    // over NN*64 float4
    float4 v = ((const float4*)X)[i];
    v.x = to_tf32(v.x); v.y = to_tf32(v.y); v.z = to_tf32(v.z); v.w = to_tf32(v.w);
    ((float4*)g_xr)[i] = v;
}

// ---------------- weight prep: [K,N] -> [n][K] permuted-16-group, RNA tf32 ----------------
__global__ __launch_bounds__(256) void prep_weights_kernel(const float* __restrict__ W, int K, int sel) {
    float* dst = (sel == 0) ? g_Wt0T : (sel == 1) ? g_Wt1T : (sel == 2) ? g_Wc0T : g_Wc1T;
    int idx = blockIdx.x * 256 + threadIdx.x;   // over K*64 float4s
    if (idx >= K * 64) return;
    int k = idx >> 6;
    int n4 = idx & 63;
    float4 v = ((const float4*)W)[idx];         // W[k][4*n4 .. 4*n4+3]
    int kl = k & 15;
    int off = (k >> 4) * 16 + (kl & 3) * 4 + (kl >> 2);
    float vv[4] = {v.x, v.y, v.z, v.w};
    #pragma unroll
    for (int j = 0; j < 4; j++)
        dst[(size_t)(n4 * 4 + j) * K + off] = to_tf32(vv[j]);
}

// ---------------- edge MLP ----------------
__global__ __launch_bounds__(256) void edge_mlp_kernel(
    const float* __restrict__ ea, const unsigned int* __restrict__ ei, int estride,
    const float* __restrict__ Wm1, const float* __restrict__ bm1,
    const float* __restrict__ Wm2, const float* __restrict__ bm2)
{
    __shared__ float sW1[16 * 32];
    __shared__ float sB1[32];
    __shared__ float sW2[32];
    __shared__ float sB2;
    int tid = threadIdx.x;
    for (int i = tid; i < 512; i += 256) sW1[i] = Wm1[i];
    if (tid < 32) { sB1[tid] = bm1[tid]; sW2[tid] = Wm2[tid]; }
    if (tid == 0) sB2 = bm2[0];
    __syncthreads();

    int e = blockIdx.x * 256 + tid;
    if (e >= EE) return;

    float a[16];
    const float4* ap = (const float4*)(ea + (size_t)e * 16);
    float4 v0 = ap[0], v1 = ap[1], v2 = ap[2], v3 = ap[3];
    a[0]=v0.x; a[1]=v0.y; a[2]=v0.z; a[3]=v0.w;
    a[4]=v1.x; a[5]=v1.y; a[6]=v1.z; a[7]=v1.w;
    a[8]=v2.x; a[9]=v2.y; a[10]=v2.z; a[11]=v2.w;
    a[12]=v3.x; a[13]=v3.y; a[14]=v3.z; a[15]=v3.w;

    float s = sB2;
    #pragma unroll
    for (int j = 0; j < 32; j++) {
        float h = sB1[j];
        #pragma unroll
        for (int i = 0; i < 16; i++) h = fmaf(a[i], sW1[i * 32 + j], h);
        h = fmaxf(h, 0.f);
        s = fmaf(h, sW2[j], s);
    }
    float ew = (s > 20.f) ? s : log1pf(expf(s));
    g_ew[e] = ew;
    int r = decode_idx(ei[(size_t)estride * e]);
    atomicAdd(&g_deg[r], ew);
    atomicAdd(&g_cnt[r], 1);
}

// ---------------- parallel scan: reduce -> spine -> downsweep ----------------
#define SCAN_NB ((NN + 1023) / 1024)

__global__ __launch_bounds__(1024) void scan_reduce_kernel() {
    __shared__ int sw[32];
    int b = blockIdx.x, tid = threadIdx.x;
    int i = b * 1024 + tid;
    int s = (i < NN) ? g_cnt[i] : 0;
    #pragma unroll
    for (int o = 16; o; o >>= 1) s += __shfl_down_sync(~0u, s, o);
    if ((tid & 31) == 0) sw[tid >> 5] = s;
    __syncthreads();
    if (tid < 32) {
        int t = sw[tid];
        #pragma unroll
        for (int o = 16; o; o >>= 1) t += __shfl_down_sync(~0u, t, o);
        if (tid == 0) g_bsum[b] = t;
    }
}

__global__ __launch_bounds__(64) void scan_spine_kernel() {
    __shared__ int sh[64];
    int tid = threadIdx.x;
    int v = (tid < SCAN_NB) ? g_bsum[tid] : 0;
    sh[tid] = v;
    __syncthreads();
    #pragma unroll
    for (int o = 1; o < 64; o <<= 1) {
        int t = (tid >= o) ? sh[tid - o] : 0;
        __syncthreads();
        sh[tid] += t;
        __syncthreads();
    }
    if (tid < SCAN_NB) g_boff[tid] = sh[tid] - v;
    if (tid == 0) g_offs[NN] = sh[SCAN_NB - 1];
}

__global__ __launch_bounds__(1024) void scan_final_kernel() {
    __shared__ int wsum[32];
    int b = blockIdx.x, tid = threadIdx.x;
    int lane = tid & 31, wd = tid >> 5;
    int i = b * 1024 + tid;
    int v = (i < NN) ? g_cnt[i] : 0;
    int incl = v;
    #pragma unroll
    for (int o = 1; o < 32; o <<= 1) {
        int t = __shfl_up_sync(~0u, incl, o);
        if (lane >= o) incl += t;
    }
    if (lane == 31) wsum[wd] = incl;
    __syncthreads();
    if (tid < 32) {
        int t = wsum[tid];
        int inc = t;
        #pragma unroll
        for (int o = 1; o < 32; o <<= 1) {
            int u = __shfl_up_sync(~0u, inc, o);
            if (tid >= o) inc += u;
        }
        wsum[tid] = inc - t;
    }
    __syncthreads();
    if (i < NN) {
        int excl = incl - v + wsum[wd] + g_boff[b];
        g_offs[i] = excl;
        g_cursor[i] = excl;
        float d = g_deg[i];
        if (d < 0.5f) d += 1.0f;
        g_dinv[i] = 1.0f / d;
    }
}

// ---------------- scatter into CSR ----------------
__global__ __launch_bounds__(256) void scatter_kernel(const unsigned int* __restrict__ ei, int estride) {
    int e = blockIdx.x * 256 + threadIdx.x;
    if (e >= EE) return;
    int r = decode_idx(ei[(size_t)estride * e]);
    int c = decode_idx(ei[(size_t)estride * (EE + e)]);
    int pos = atomicAdd(&g_cursor[r], 1);
    g_ccol[pos] = c;
    g_cw[pos] = g_ew[e] * g_dinv[r];
}

// ---------------- dual GEMM: mma.sync tf32, full cp.async staging, 4-stage ring ----------------
// CTA: 64 M x 128 N x both branches; grid (782, 2); warp tile 64x32 per branch.
// A per stage: row-major [64][APITCH=20] (padded -> conflict-free LDSM) = 1280 floats
// B per stage: [n(256)][16] permuted word order                          = 4096 floats
#define APITCH 20
#define A_PK  (64 * APITCH)
#define B_PK  4096
#define STAGEF (A_PK + B_PK)        // 5376 floats
#define NSTAGE 4
#define SMEM_DYN (NSTAGE * STAGEF * 4)   // 86016 bytes

template <bool FINAL>
__global__ __launch_bounds__(256, 2) void tc_mma_gemm(
    const unsigned int* __restrict__ mask,
    const float* __restrict__ bias0, const float* __restrict__ bias1,
    float* __restrict__ Out)
{
    constexpr int K = FINAL ? 512 : 256;
    constexpr int NC = K / 16;
    extern __shared__ float smf[];
    __shared__ float sb0[256], sb1[256];

    int tid  = threadIdx.x;
    int lane = tid & 31;
    int w    = tid >> 5;
    int wm   = w & 1;          // row half: wm*32
    int wn   = w >> 1;         // col group: wn*32
    int m0   = blockIdx.x * 64;
    int n0   = blockIdx.y * 128;

    sb0[tid] = bias0[tid];
    sb1[tid] = bias1[tid];
    __syncthreads();

    const float* BT0 = FINAL ? g_Wc0T : g_Wt0T;
    const float* BT1 = FINAL ? g_Wc1T : g_Wt1T;
    const uint32_t smbase = smem_u32(smf);

    float acc[2][2][4][4];     // [branch][mfrag][nfrag][reg]
    #pragma unroll
    for (int b = 0; b < 2; b++)
        #pragma unroll
        for (int f = 0; f < 2; f++)
            #pragma unroll
            for (int g = 0; g < 4; g++)
                #pragma unroll
                for (int r = 0; r < 4; r++) acc[b][f][g][r] = 0.f;

    // A staging: thread -> (row, float4 slot)
    const int arow = tid >> 2;            // 0..63
    const int q    = tid & 3;             // float4 k-slot

    // ldmatrix per-lane source row/k within the warp's A view
    const int ltile = lane >> 3;                       // 0..3
    const int lrow  = ((ltile & 1) << 3) + (lane & 7); // row within 16-row frag
    const int lk    = (ltile >> 1) << 2;               // 0 or 4

    auto stage_async = [&](int c, int slot) {
        // A: one 16B cp.async per thread
        {
            const float* src;
            if (!FINAL) {
                src = g_xr + (size_t)(m0 + arow) * 256 + c * 16 + q * 4;
            } else if (c < 16) {
                src = g_ar + (size_t)(m0 + arow) * 256 + c * 16 + q * 4;
            } else {
                src = g_xr + (size_t)(m0 + arow) * 256 + (c - 16) * 16 + q * 4;
            }
            uint32_t dst = smbase + (uint32_t)(slot * STAGEF + arow * APITCH + q * 4) * 4;
            CP_ASYNC16(dst, src);
        }
        // B: four 16B cp.async per thread (256 n-rows x 4 quads)
        #pragma unroll
        for (int i = 0; i < 4; i++) {
            int idx = tid + i * 256;
            int nr = idx >> 2, j4 = idx & 3;
            int br = nr >> 7;
            int nn = (nr & 127) + n0;
            const float* src = (br ? BT1 : BT0) + (size_t)nn * K + c * 16 + j4 * 4;
            uint32_t dst = smbase + (uint32_t)(slot * STAGEF + A_PK + nr * 16 + j4 * 4) * 4;
            CP_ASYNC16(dst, src);
        }
    };
    auto compute = [&](int slot) {
        uint32_t abase = smbase + (uint32_t)(slot * STAGEF) * 4;
        const float* sB = smf + slot * STAGEF + A_PK;
        uint32_t a[2][2][4];   // [ks][mfrag][reg]
        #pragma unroll
        for (int ks = 0; ks < 2; ks++)
            #pragma unroll
            for (int f = 0; f < 2; f++) {
                int row = wm * 32 + f * 16 + lrow;
                uint32_t addr = abase + (uint32_t)(row * APITCH + ks * 8 + lk) * 4;
                LDMATRIX_X4(a[ks][f][0], a[ks][f][1], a[ks][f][2], a[ks][f][3], addr);
            }
        #pragma unroll
        for (int br = 0; br < 2; br++) {
            #pragma unroll
            for (int g = 0; g < 4; g++) {
                int n = br * 128 + wn * 32 + g * 8 + (lane >> 2);
                float4 bb = *(const float4*)&sB[n * 16 + (lane & 3) * 4];
                uint32_t b00 = fbits(bb.x), b01 = fbits(bb.y);
                uint32_t b10 = fbits(bb.z), b11 = fbits(bb.w);
                MMA_TF32(acc[br][0][g], a[0][0], b00, b01);
                MMA_TF32(acc[br][1][g], a[0][1], b00, b01);
                MMA_TF32(acc[br][0][g], a[1][0], b10, b11);
                MMA_TF32(acc[br][1][g], a[1][1], b10, b11);
            }
        }
    };

    // prologue: 3 stages in flight
    #pragma unroll
    for (int c = 0; c < 3; c++) { stage_async(c, c); CP_COMMIT(); }

    for (int c = 0; c < NC; c++) {
        CP_WAIT2();              // group c drained (groups complete in order)
        __syncthreads();         // cross-warp visibility + slot reuse safety
        if (c + 3 < NC) stage_async(c + 3, (c + 3) & 3);
        CP_COMMIT();             // empty group in tail keeps the count uniform
        compute(c & 3);
    }

    // ---- epilogue: bias (+relu) + register-local masked mix ----
    float* dst = FINAL ? Out : g_xm;
    #pragma unroll
    for (int f = 0; f < 2; f++) {
        int r0 = m0 + wm * 32 + f * 16 + (lane >> 2);
        int r1 = r0 + 8;
        unsigned mk0 = (r0 < NN) ? mask[r0] : 0u;
        unsigned mk1 = (r1 < NN) ? mask[r1] : 0u;
        float za0 = mk0 ? (1.f - ZMIX) : ZMIX, zb0 = mk0 ? ZMIX : (1.f - ZMIX);
        float za1 = mk1 ? (1.f - ZMIX) : ZMIX, zb1 = mk1 ? ZMIX : (1.f - ZMIX);
        #pragma unroll
        for (int g = 0; g < 4; g++) {
            int col = n0 + wn * 32 + g * 8 + (lane & 3) * 2;
            float v00 = acc[0][f][g][0] + sb0[col];
            float v01 = acc[0][f][g][1] + sb0[col + 1];
            float v10 = acc[1][f][g][0] + sb1[col];
            float v11 = acc[1][f][g][1] + sb1[col + 1];
            float u00 = acc[0][f][g][2] + sb0[col];
            float u01 = acc[0][f][g][3] + sb0[col + 1];
            float u10 = acc[1][f][g][2] + sb1[col];
            float u11 = acc[1][f][g][3] + sb1[col + 1];
            if (!FINAL) {
                v00 = fmaxf(v00, 0.f); v01 = fmaxf(v01, 0.f);
                v10 = fmaxf(v10, 0.f); v11 = fmaxf(v11, 0.f);
                u00 = fmaxf(u00, 0.f); u01 = fmaxf(u01, 0.f);
                u10 = fmaxf(u10, 0.f); u11 = fmaxf(u11, 0.f);
            }
            if (r0 < NN) {
                float2 o = make_float2(za0 * v00 + zb0 * v10, za0 * v01 + zb0 * v11);
                *(float2*)&dst[(size_t)r0 * 256 + col] = o;
            }
            if (r1 < NN) {
                float2 o = make_float2(za1 * u00 + zb1 * u10, za1 * u01 + zb1 * u11);
                *(float2*)&dst[(size_t)r1 * 256 + col] = o;
            }
        }
    }
}

// ---------------- aggregation: one block per row, gather over CSR ----------------
__global__ __launch_bounds__(256) void agg_kernel() {
    int r = blockIdx.x;
    int d = threadIdx.x;
    int beg = g_offs[r], end = g_offs[r + 1];
    float acc = 0.f;
    for (int j = beg; j < end; j++) {
        int c = g_ccol[j];
        float w = g_cw[j];
        acc = fmaf(w, g_xm[(size_t)c * DOUTC + d], acc);
    }
    g_agg[(size_t)r * DOUTC + d] = acc;
}

// ---------------- column stats ----------------
__global__ __launch_bounds__(256) void colstats_kernel() {
    int d = threadIdx.x;
    float s = 0.f, s2 = 0.f;
    for (int r = blockIdx.x; r < NN; r += gridDim.x) {
        float v = g_agg[(size_t)r * DOUTC + d];
        s += v;
        s2 = fmaf(v, v, s2);
    }
    atomicAdd(&g_colsum[d], s);
    atomicAdd(&g_colsq[d], s2);
}

// ---------------- GraphNorm params ----------------
__global__ __launch_bounds__(256) void normparams_kernel(
    const float* __restrict__ gn_w, const float* __restrict__ gn_b,
    const float* __restrict__ gn_alpha)
{
    int d = threadIdx.x;
    float m = g_colsum[d] * (1.0f / NN);
    float a = gn_alpha[d];
    float var = g_colsq[d] * (1.0f / NN) + m * m * (a * a - 2.f * a);
    float rstd = rsqrtf(var + EPSGN);
    float s = gn_w[d] * rstd;
    g_ns[d] = s;
    g_nt[d] = gn_b[d] - s * a * m;
}

// ---------------- norm apply: g_ar = rna(ns*agg + nt) ----------------
__global__ __launch_bounds__(256) void normapply_kernel() {
    __shared__ float sns[256], snt[256];
    int tid = threadIdx.x;
    sns[tid] = g_ns[tid];
    snt[tid] = g_nt[tid];
    __syncthreads();
    int i = blockIdx.x * 256 + tid;            // over NN*64 float4
    int c4 = (i & 63) * 4;
    float4 v = ((const float4*)g_agg)[i];
    float4 r;
    r.x = to_tf32(fmaf(sns[c4 + 0], v.x, snt[c4 + 0]));
    r.y = to_tf32(fmaf(sns[c4 + 1], v.y, snt[c4 + 1]));
    r.z = to_tf32(fmaf(sns[c4 + 2], v.z, snt[c4 + 2]));
    r.w = to_tf32(fmaf(sns[c4 + 3], v.w, snt[c4 + 3]));
    ((float4*)g_ar)[i] = r;
}

// ---------------- launch ----------------
extern "C" void kernel_launch(void* const* d_in, const int* in_sizes, int n_in,
                              void* d_out, int out_size)
{
    const float*        x      = (const float*)d_in[0];
    const unsigned int* ei     = (const unsigned int*)d_in[1];
    const unsigned int* mask   = (const unsigned int*)d_in[3];
    const float*        ea     = (const float*)d_in[4];
    const float*        Wt0    = (const float*)d_in[5];
    const float*        bt0    = (const float*)d_in[6];
    const float*        Wt1    = (const float*)d_in[7];
    const float*        bt1    = (const float*)d_in[8];
    const float*        Wc0    = (const float*)d_in[9];
    const float*        bc0    = (const float*)d_in[10];
    const float*        Wc1    = (const float*)d_in[11];
    const float*        bc1    = (const float*)d_in[12];
    const float*        gn_w   = (const float*)d_in[13];
    const float*        gn_b   = (const float*)d_in[14];
    const float*        gn_a   = (const float*)d_in[15];
    const float*        Wm1    = (const float*)d_in[16];
    const float*        bm1    = (const float*)d_in[17];
    const float*        Wm2    = (const float*)d_in[18];
    const float*        bm2    = (const float*)d_in[19];
    float*              out    = (float*)d_out;

    int estride = (in_sizes[1] >= 4 * EE) ? 2 : 1;

    cudaFuncSetAttribute(tc_mma_gemm<false>,
                         cudaFuncAttributeMaxDynamicSharedMemorySize, SMEM_DYN);
    cudaFuncSetAttribute(tc_mma_gemm<true>,
                         cudaFuncAttributeMaxDynamicSharedMemorySize, SMEM_DYN);

    dim3 ggrid((NN + 63) / 64, 2);

    // GEMM1 at launch idx 3 for ncu observability.
    prep_x_kernel<<<NN * 64 / 256, 256>>>(x);
    prep_weights_kernel<<<64, 256>>>(Wt0, 256, 0);
    prep_weights_kernel<<<64, 256>>>(Wt1, 256, 1);
    // xm = mix(mask, relu(x@Wt1+bt1), relu(x@Wt0+bt0)) -> g_xm
    tc_mma_gemm<false><<<ggrid, 256, SMEM_DYN>>>(mask, bt0, bt1, nullptr);
    init_kernel<<<256, 256>>>();
    prep_weights_kernel<<<128, 256>>>(Wc0, 512, 2);
    prep_weights_kernel<<<128, 256>>>(Wc1, 512, 3);
    edge_mlp_kernel<<<(EE + 255) / 256, 256>>>(ea, ei, estride, Wm1, bm1, Wm2, bm2);
    scan_reduce_kernel<<<SCAN_NB, 1024>>>();
    scan_spine_kernel<<<1, 64>>>();
    scan_final_kernel<<<SCAN_NB, 1024>>>();
    scatter_kernel<<<(EE + 255) / 256, 256>>>(ei, estride);

    agg_kernel<<<NN, 256>>>();
    colstats_kernel<<<512, 256>>>();
    normparams_kernel<<<1, 256>>>(gn_w, gn_b, gn_a);
    normapply_kernel<<<NN * 64 / 256, 256>>>();

    // out = mix(mask, xc@Wc1+bc1, xc@Wc0+bc0), xc = [norm(agg) | x]
    tc_mma_gemm<true><<<ggrid, 256, SMEM_DYN>>>(mask, bc0, bc1, out);
}